// round 14
// baseline (speedup 1.0000x reference)
#include <cuda_runtime.h>
#include <cuda_fp16.h>
#include <cstdint>

#define NDRUG 100000
#define NPROT 100000
#define NN    100000
#define NEMAX 800000
#define DIM   128
#define KC    32        // k-chunk
#define SAKH  40        // smem chunk row stride (fp16 units, 80B: conflict-free)
#define GBLK  782       // ceil(100000/128)

// ---------------- scratch ----------------
// pre-scaled fp16 feature buffers (ping-pong A/B):
//   *_d  : drug features scaled by rsqrt(ddi_out)
//   *_p1 : protein features scaled by rsqrt(pdi_out)
//   *_p2 : protein features scaled by rsqrt(ppi_out)
__device__ __half g_sA_d [(size_t)NN * DIM];
__device__ __half g_sA_p1[(size_t)NN * DIM];
__device__ __half g_sA_p2[(size_t)NN * DIM];
__device__ __half g_sB_d [(size_t)NN * DIM];
__device__ __half g_sB_p1[(size_t)NN * DIM];
__device__ __half g_sB_p2[(size_t)NN * DIM];
__device__ __half g_agg1[(size_t)NDRUG * DIM];
__device__ __half g_agg2[(size_t)NDRUG * DIM];
__device__ __half g_aggp[(size_t)NPROT * DIM];
// int degree counts: [0]=ddi_out [1]=ddi_in [2]=pdi_out [3]=pdi_in [4]=ppi_out [5]=ppi_in
__device__ int g_cnt[6 * NN];
__device__ __half g_Wt[(size_t)9 * DIM * DIM];  // transposed fp16 weights [layer][rel][n][k]
__device__ int g_indptr[3 * (NN + 1)];
__device__ int g_cursor[3 * NN];
__device__ int g_eidx[3 * NEMAX];
__device__ int g_bsum[3 * 128];

// ---------------- helpers ----------------
__device__ __forceinline__ uint32_t sptr(const void* p) {
    return (uint32_t)__cvta_generic_to_shared(p);
}
__device__ __forceinline__ void cp_async16(uint32_t dst, const void* src, int sz) {
    asm volatile("cp.async.cg.shared.global [%0], [%1], 16, %2;" :: "r"(dst), "l"(src), "r"(sz));
}
__device__ __forceinline__ void mma_f16(float c[4], const uint32_t a[4], const uint32_t b[2]) {
    asm volatile(
        "mma.sync.aligned.m16n8k16.row.col.f32.f16.f16.f32 "
        "{%0,%1,%2,%3}, {%4,%5,%6,%7}, {%8,%9}, {%0,%1,%2,%3};"
        : "+f"(c[0]), "+f"(c[1]), "+f"(c[2]), "+f"(c[3])
        : "r"(a[0]), "r"(a[1]), "r"(a[2]), "r"(a[3]), "r"(b[0]), "r"(b[1]));
}
__device__ __forceinline__ float rs_of(int c) {
    return rsqrtf(fmaxf((float)c, 1.0f));
}

// ---------------- prep: transpose W to fp16 [n][k] + zero counts ----------------
#define PREP_X 2344
__global__ void prep_kernel(const float* __restrict__ Wa, const float* __restrict__ Wb,
                            const float* __restrict__ Wc, __half* __restrict__ Wt,
                            int* __restrict__ cnt) {
    const int y = blockIdx.y;
    if (y == 0) {
        for (int i = blockIdx.x * 256 + threadIdx.x; i < 9 * DIM * DIM; i += PREP_X * 256) {
            int grp = i / (3 * DIM * DIM);
            int rem3 = i - grp * 3 * DIM * DIM;
            const float* W = grp == 0 ? Wa : (grp == 1 ? Wb : Wc);
            int rel = rem3 >> 14, rem = rem3 & 16383;
            int k = rem >> 7, n = rem & 127;
            Wt[i - rem + (n << 7) + k] = __float2half_rn(W[(rel << 14) + (k << 7) + n]);
        }
    } else {
        int i = blockIdx.x * 256 + threadIdx.x;
        if (i < 6 * NN) cnt[i] = 0;
    }
}

// ---------------- batched degree count (int) ----------------
__global__ void count2b(const int* __restrict__ s0, const int* __restrict__ d0, int n0,
                        const int* __restrict__ s1, const int* __restrict__ d1, int n1,
                        const int* __restrict__ s2, const int* __restrict__ d2, int n2,
                        int* __restrict__ cnt) {
    const int rel = blockIdx.y;
    const int* src = rel == 0 ? s0 : (rel == 1 ? s1 : s2);
    const int* dst = rel == 0 ? d0 : (rel == 1 ? d1 : d2);
    int n = rel == 0 ? n0 : (rel == 1 ? n1 : n2);
    int* cs = cnt + (size_t)(2 * rel) * NN;
    int* cd = cnt + (size_t)(2 * rel + 1) * NN;
    int i = blockIdx.x * blockDim.x + threadIdx.x;
    if (i < n) {
        atomicAdd(&cs[src[i]], 1);
        atomicAdd(&cd[dst[i]], 1);
    }
}

// ---------------- scale fp32 inputs into pre-scaled fp16 buffers (inline rsqrt) ----------------
__global__ void scale_inputs(const float* __restrict__ fd, const float* __restrict__ fp,
                             const int* __restrict__ cnt,
                             __half* __restrict__ sd, __half* __restrict__ sp1,
                             __half* __restrict__ sp2) {
    const int y = blockIdx.y;
    const float* f    = (y == 0) ? fd : fp;
    const int* cv     = cnt + (size_t)(2 * y) * NN;   // out-counts per relation
    __half* o = (y == 0) ? sd : ((y == 1) ? sp1 : sp2);
    const int n4 = NN * DIM / 4;
    int i = blockIdx.x * blockDim.x + threadIdx.x;
    if (i < n4) {
        float sc = rs_of(__ldg(cv + (i >> 5)));
        float4 v = __ldg(reinterpret_cast<const float4*>(f) + i);
        reinterpret_cast<__half2*>(o)[2 * i]     = __floats2half2_rn(v.x * sc, v.y * sc);
        reinterpret_cast<__half2*>(o)[2 * i + 1] = __floats2half2_rn(v.z * sc, v.w * sc);
    }
}

// ---------------- scans ----------------
__global__ void scan1(const int* __restrict__ cnt, int* __restrict__ indptr,
                      int* __restrict__ bsum) {
    __shared__ int sm2[1024];
    const int rel = blockIdx.y;
    const int* c = cnt + (size_t)(2 * rel + 1) * NN;
    int* excl = indptr + rel * (NN + 1);
    int tid = threadIdx.x;
    int i = blockIdx.x * 1024 + tid;
    int v = (i < NN) ? __ldg(c + i) : 0;
    sm2[tid] = v;
    __syncthreads();
#pragma unroll
    for (int off = 1; off < 1024; off <<= 1) {
        int t2 = (tid >= off) ? sm2[tid - off] : 0;
        __syncthreads();
        sm2[tid] += t2;
        __syncthreads();
    }
    if (i < NN) excl[i] = sm2[tid] - v;
    if (tid == 1023) bsum[rel * 128 + blockIdx.x] = sm2[1023];
}
__global__ void scan3m(const int* __restrict__ cnt, int* __restrict__ indptr,
                       const int* __restrict__ bsum, int* __restrict__ cursor) {
    const int rel = blockIdx.y;
    const int* c = cnt + (size_t)(2 * rel + 1) * NN;
    int* excl = indptr + rel * (NN + 1);
    int i = blockIdx.x * blockDim.x + threadIdx.x;
    if (i < NN) {
        int b = i >> 10;
        int off = 0;
        for (int j = 0; j < b; j++) off += bsum[rel * 128 + j];
        int e = excl[i] + off;
        excl[i] = e;
        cursor[rel * NN + i] = e;
        if (i == NN - 1) excl[NN] = e + __ldg(c + i);
    }
}
// CSR fill
__global__ void fill3_kernel(const int* __restrict__ s0, const int* __restrict__ d0, int n0,
                             const int* __restrict__ s1, const int* __restrict__ d1, int n1,
                             const int* __restrict__ s2, const int* __restrict__ d2, int n2,
                             int* __restrict__ cursor, int* __restrict__ eidx) {
    const int y = blockIdx.y;
    const int* src = y == 0 ? s0 : (y == 1 ? s1 : s2);
    const int* dst = y == 0 ? d0 : (y == 1 ? d1 : d2);
    int nE = y == 0 ? n0 : (y == 1 ? n1 : n2);
    int e = blockIdx.x * blockDim.x + threadIdx.x;
    if (e < nE) {
        int p = atomicAdd(&cursor[y * NN + dst[e]], 1);
        eidx[(size_t)y * NEMAX + p] = src[e];
    }
}

// ---------------- batched CSR gather: half-warp per row, 8/4/1 MLP tiers ----------------
__global__ void __launch_bounds__(256)
gather3(const __half* __restrict__ sd, const __half* __restrict__ sp1,
        const __half* __restrict__ sp2,
        const int* __restrict__ indptr, const int* __restrict__ eidx,
        const int* __restrict__ cnt,
        __half* __restrict__ agg1, __half* __restrict__ agg2, __half* __restrict__ aggp) {
    const int rel = blockIdx.y;
    const __half* h = (rel == 0) ? sd : ((rel == 1) ? sp1 : sp2);
    const int* ip = indptr + rel * (NN + 1);
    const int* ei = eidx + (size_t)rel * NEMAX;
    const int* ci = cnt + (size_t)(2 * rel + 1) * NN;   // in-counts
    __half* agg = (rel == 0) ? agg1 : ((rel == 1) ? agg2 : aggp);

    int row  = (blockIdx.x * blockDim.x + threadIdx.x) >> 4;
    int lane = threadIdx.x & 15;
    if (row >= NN) return;
    int s0 = __ldg(ip + row), s1 = __ldg(ip + row + 1);
    float accf[8];
#pragma unroll
    for (int j = 0; j < 8; j++) accf[j] = 0.0f;

    for (int base = s0; base < s1; base += 16) {
        int m = min(16, s1 - base);
        int se = (lane < m) ? __ldg(ei + base + lane) : 0;
        int j = 0;
        // 8-edge preload tier (deep MLP)
        for (; j + 8 <= m; j += 8) {
            uint4 r[8];
#pragma unroll
            for (int q = 0; q < 8; q++) {
                int s = __shfl_sync(0xFFFFFFFFu, se, j + q, 16);
                r[q] = __ldg(reinterpret_cast<const uint4*>(h + (size_t)s * DIM) + lane);
            }
#pragma unroll
            for (int q = 0; q < 8; q++) {
                const __half2* hh = reinterpret_cast<const __half2*>(&r[q]);
#pragma unroll
                for (int k = 0; k < 4; k++) {
                    float2 f = __half22float2(hh[k]);
                    accf[2 * k]     += f.x;
                    accf[2 * k + 1] += f.y;
                }
            }
        }
        // 4-edge tier
        if (j + 4 <= m) {
            uint4 r[4];
#pragma unroll
            for (int q = 0; q < 4; q++) {
                int s = __shfl_sync(0xFFFFFFFFu, se, j + q, 16);
                r[q] = __ldg(reinterpret_cast<const uint4*>(h + (size_t)s * DIM) + lane);
            }
#pragma unroll
            for (int q = 0; q < 4; q++) {
                const __half2* hh = reinterpret_cast<const __half2*>(&r[q]);
#pragma unroll
                for (int k = 0; k < 4; k++) {
                    float2 f = __half22float2(hh[k]);
                    accf[2 * k]     += f.x;
                    accf[2 * k + 1] += f.y;
                }
            }
            j += 4;
        }
        // remainder
        for (; j < m; j++) {
            int s = __shfl_sync(0xFFFFFFFFu, se, j, 16);
            uint4 r = __ldg(reinterpret_cast<const uint4*>(h + (size_t)s * DIM) + lane);
            const __half2* hh = reinterpret_cast<const __half2*>(&r);
#pragma unroll
            for (int k = 0; k < 4; k++) {
                float2 f = __half22float2(hh[k]);
                accf[2 * k]     += f.x;
                accf[2 * k + 1] += f.y;
            }
        }
    }
    float ri = rs_of(__ldg(ci + row));
    uint4 o;
    __half2* oh = reinterpret_cast<__half2*>(&o);
#pragma unroll
    for (int j = 0; j < 4; j++)
        oh[j] = __floats2half2_rn(accf[2 * j] * ri, accf[2 * j + 1] * ri);
    reinterpret_cast<uint4*>(agg + (size_t)row * DIM)[lane] = o;
}

// ---------------- cp.async double-buffered fp16 HMMA GEMM ----------------
template<bool RELU, bool TWO, bool F16OUT>
__device__ __forceinline__ void gemm_body(
    int bx, const __half* __restrict__ A1, const __half* __restrict__ A2,
    const __half* __restrict__ Wt1, const __half* __restrict__ Wt2,
    const float* __restrict__ b1, const float* __restrict__ b2,
    void* __restrict__ out1, void* __restrict__ out2,
    const int* __restrict__ cnt1, const int* __restrict__ cnt2,
    int nrows, __half* sm) {
    __half* As = sm;
    __half* Ws = sm + 2 * 128 * SAKH;

    const int t = threadIdx.x;
    const int lane = t & 31, wid = t >> 5;
    const int wm = wid >> 2, wn = wid & 3;
    const int row0 = bx * 128;
    const int qid = lane >> 2, qtl = lane & 3;

    float acc[4][4][4];
#pragma unroll
    for (int mi = 0; mi < 4; mi++)
#pragma unroll
        for (int ni = 0; ni < 4; ni++)
#pragma unroll
            for (int j = 0; j < 4; j++) acc[mi][ni][j] = 0.0f;

    const int C = TWO ? 8 : 4;

    auto issue = [&](int c) {
        int sidx = TWO ? (c >> 2) : 0;
        int kc   = TWO ? (c & 3) : c;
        const __half* A = sidx ? A2 : A1;
        const __half* W = sidx ? Wt2 : Wt1;
        int stage = c & 1;
        __half* as = As + stage * 128 * SAKH;
        __half* ws = Ws + stage * 128 * SAKH;
#pragma unroll
        for (int i = 0; i < 2; i++) {
            int idx = t + 256 * i;
            int r = idx >> 2, c4 = idx & 3;
            int row = row0 + r;
            int sz = (row < nrows) ? 16 : 0;
            cp_async16(sptr(as + r * SAKH + c4 * 8), A + (size_t)row * DIM + kc * KC + c4 * 8, sz);
            cp_async16(sptr(ws + r * SAKH + c4 * 8), W + (size_t)r * DIM + kc * KC + c4 * 8, 16);
        }
        asm volatile("cp.async.commit_group;" ::: "memory");
    };

    issue(0);
    issue(1);
    for (int c = 0; c < C; c++) {
        if (c == C - 1) asm volatile("cp.async.wait_group 0;" ::: "memory");
        else            asm volatile("cp.async.wait_group 1;" ::: "memory");
        __syncthreads();
        const int stage = c & 1;
        const __half* as = As + stage * 128 * SAKH;
        const __half* ws = Ws + stage * 128 * SAKH;
#pragma unroll
        for (int ks = 0; ks < 2; ks++) {
            const int k0 = ks * 16;
            uint32_t a[4][4], bf[4][2];
#pragma unroll
            for (int mi = 0; mi < 4; mi++) {
                const __half* p = &as[(wm * 64 + mi * 16 + qid) * SAKH + k0 + 2 * qtl];
                a[mi][0] = *reinterpret_cast<const uint32_t*>(p);
                a[mi][1] = *reinterpret_cast<const uint32_t*>(p + 8 * SAKH);
                a[mi][2] = *reinterpret_cast<const uint32_t*>(p + 8);
                a[mi][3] = *reinterpret_cast<const uint32_t*>(p + 8 * SAKH + 8);
            }
#pragma unroll
            for (int ni = 0; ni < 4; ni++) {
                const __half* p = &ws[(wn * 32 + ni * 8 + qid) * SAKH + k0 + 2 * qtl];
                bf[ni][0] = *reinterpret_cast<const uint32_t*>(p);
                bf[ni][1] = *reinterpret_cast<const uint32_t*>(p + 8);
            }
#pragma unroll
            for (int mi = 0; mi < 4; mi++)
#pragma unroll
                for (int ni = 0; ni < 4; ni++)
                    mma_f16(acc[mi][ni], a[mi], bf[ni]);
        }
        __syncthreads();
        if (c + 2 < C) issue(c + 2);
    }

    // Epilogue
#pragma unroll
    for (int ni = 0; ni < 4; ni++) {
        int col = wn * 32 + ni * 8 + qtl * 2;
        float bb0 = __ldg(b1 + col)     + (TWO ? __ldg(b2 + col)     : 0.0f);
        float bb1 = __ldg(b1 + col + 1) + (TWO ? __ldg(b2 + col + 1) : 0.0f);
#pragma unroll
        for (int mi = 0; mi < 4; mi++) {
#pragma unroll
            for (int half = 0; half < 2; half++) {
                int r = row0 + wm * 64 + mi * 16 + qid + half * 8;
                if (r < nrows) {
                    float ox = acc[mi][ni][half * 2 + 0] + bb0;
                    float oy = acc[mi][ni][half * 2 + 1] + bb1;
                    if (RELU) { ox = fmaxf(ox, 0.0f); oy = fmaxf(oy, 0.0f); }
                    if (F16OUT) {
                        float sA = rs_of(__ldg(cnt1 + r));
                        *reinterpret_cast<__half2*>(
                            (__half*)out1 + (size_t)r * DIM + col) =
                            __floats2half2_rn(ox * sA, oy * sA);
                        if (!TWO) {
                            float sB = rs_of(__ldg(cnt2 + r));
                            *reinterpret_cast<__half2*>(
                                (__half*)out2 + (size_t)r * DIM + col) =
                                __floats2half2_rn(ox * sB, oy * sB);
                        }
                    } else {
                        float2 o; o.x = ox; o.y = oy;
                        *reinterpret_cast<float2*>((float*)out1 + (size_t)r * DIM + col) = o;
                    }
                }
            }
        }
    }
}

template<bool RELU, bool F16OUT>
__global__ void __launch_bounds__(256)
layer_mma(const __half* __restrict__ agg1, const __half* __restrict__ agg2,
          const __half* __restrict__ aggp, const __half* __restrict__ Wt,
          const float* __restrict__ bb, const int* __restrict__ cnt,
          void* __restrict__ outd, void* __restrict__ outp1, void* __restrict__ outp2,
          int split) {
    extern __shared__ __half smh[];
    if ((int)blockIdx.x < split)
        gemm_body<RELU, true, F16OUT>(blockIdx.x, agg1, agg2,
                                      Wt, Wt + DIM * DIM, bb, bb + DIM,
                                      outd, nullptr, cnt + 0 * NN, nullptr, NDRUG, smh);
    else
        gemm_body<RELU, false, F16OUT>(blockIdx.x - split, aggp, nullptr,
                                       Wt + 2 * DIM * DIM, nullptr, bb + 2 * DIM, nullptr,
                                       outp1, outp2, cnt + 2 * NN, cnt + 4 * NN, NPROT, smh);
}

// ---------------- host orchestration ----------------
static const size_t GEMM_SMEM = 4u * 128u * SAKH * sizeof(__half);  // 40960 B

template<bool RELU, bool F16OUT>
static void launch_layer(const __half* sd, const __half* sp1, const __half* sp2,
                         void* od, void* op1, void* op2,
                         const __half* Wt, const float* b,
                         int* indptr, int* eidx,
                         __half* agg1, __half* agg2, __half* aggp, int* cnt) {
    gather3<<<dim3((NN * 16 + 255) / 256, 3), 256>>>(sd, sp1, sp2, indptr, eidx, cnt,
                                                     agg1, agg2, aggp);
    layer_mma<RELU, F16OUT><<<2 * GBLK, 256, GEMM_SMEM>>>(agg1, agg2, aggp, Wt, b, cnt,
                                                          od, op1, op2, GBLK);
}

extern "C" void kernel_launch(void* const* d_in, const int* in_sizes, int n_in,
                              void* d_out, int out_size) {
    const float* hd0   = (const float*)d_in[0];
    const float* hp0   = (const float*)d_in[1];
    const int*   ddi_s = (const int*)d_in[2];
    const int*   ddi_d = (const int*)d_in[3];
    const int*   pdi_s = (const int*)d_in[4];
    const int*   pdi_d = (const int*)d_in[5];
    const int*   ppi_s = (const int*)d_in[6];
    const int*   ppi_d = (const int*)d_in[7];
    const float* W1 = (const float*)d_in[8];
    const float* b1 = (const float*)d_in[9];
    const float* W2 = (const float*)d_in[10];
    const float* b2 = (const float*)d_in[11];
    const float* W3 = (const float*)d_in[12];
    const float* b3 = (const float*)d_in[13];

    const int nE_ddi = in_sizes[2];
    const int nE_pdi = in_sizes[4];
    const int nE_ppi = in_sizes[6];

    cudaFuncSetAttribute(layer_mma<true, true>,   cudaFuncAttributeMaxDynamicSharedMemorySize, (int)GEMM_SMEM);
    cudaFuncSetAttribute(layer_mma<false, false>, cudaFuncAttributeMaxDynamicSharedMemorySize, (int)GEMM_SMEM);

    __half *agg1, *agg2, *aggp, *wt;
    __half *sA_d, *sA_p1, *sA_p2, *sB_d, *sB_p1, *sB_p2;
    int *cnt, *indptr, *cursor, *eidx, *bsum;
    cudaGetSymbolAddress((void**)&sA_d,  g_sA_d);
    cudaGetSymbolAddress((void**)&sA_p1, g_sA_p1);
    cudaGetSymbolAddress((void**)&sA_p2, g_sA_p2);
    cudaGetSymbolAddress((void**)&sB_d,  g_sB_d);
    cudaGetSymbolAddress((void**)&sB_p1, g_sB_p1);
    cudaGetSymbolAddress((void**)&sB_p2, g_sB_p2);
    cudaGetSymbolAddress((void**)&agg1, g_agg1);
    cudaGetSymbolAddress((void**)&agg2, g_agg2);
    cudaGetSymbolAddress((void**)&aggp, g_aggp);
    cudaGetSymbolAddress((void**)&cnt, g_cnt);
    cudaGetSymbolAddress((void**)&wt, g_Wt);
    cudaGetSymbolAddress((void**)&indptr, g_indptr);
    cudaGetSymbolAddress((void**)&cursor, g_cursor);
    cudaGetSymbolAddress((void**)&eidx, g_eidx);
    cudaGetSymbolAddress((void**)&bsum, g_bsum);

    int nEmax = nE_ddi > nE_pdi ? nE_ddi : nE_pdi;
    if (nE_ppi > nEmax) nEmax = nE_ppi;

    // preprocessing
    prep_kernel<<<dim3(PREP_X, 2), 256>>>(W1, W2, W3, wt, cnt);
    count2b<<<dim3((nEmax + 255) / 256, 3), 256>>>(
        ddi_s, ddi_d, nE_ddi, pdi_s, pdi_d, nE_pdi, ppi_s, ppi_d, nE_ppi, cnt);
    scale_inputs<<<dim3((NN * DIM / 4 + 255) / 256, 3), 256>>>(
        hd0, hp0, cnt, sA_d, sA_p1, sA_p2);
    scan1<<<dim3((NN + 1023) / 1024, 3), 1024>>>(cnt, indptr, bsum);
    scan3m<<<dim3((NN + 255) / 256, 3), 256>>>(cnt, indptr, bsum, cursor);
    fill3_kernel<<<dim3((nEmax + 255) / 256, 3), 256>>>(
        ddi_s, ddi_d, nE_ddi, pdi_s, pdi_d, nE_pdi, ppi_s, ppi_d, nE_ppi, cursor, eidx);

    float* outd = (float*)d_out;
    float* outp = outd + (size_t)NDRUG * DIM;

    // layer 1: A -> B (pre-scaled fp16), ReLU
    launch_layer<true, true>(sA_d, sA_p1, sA_p2, sB_d, sB_p1, sB_p2,
                             wt + 0 * 3 * DIM * DIM, b1, indptr, eidx, agg1, agg2, aggp, cnt);
    // layer 2: B -> A, ReLU
    launch_layer<true, true>(sB_d, sB_p1, sB_p2, sA_d, sA_p1, sA_p2,
                             wt + 1 * 3 * DIM * DIM, b2, indptr, eidx, agg1, agg2, aggp, cnt);
    // layer 3: A -> fp32 d_out, no activation
    launch_layer<false, false>(sA_d, sA_p1, sA_p2, outd, outp, nullptr,
                               wt + 2 * 3 * DIM * DIM, b3, indptr, eidx, agg1, agg2, aggp, cnt);
}

// round 15
// speedup vs baseline: 1.3725x; 1.3725x over previous
#include <cuda_runtime.h>
#include <cuda_fp16.h>
#include <cstdint>

#define NDRUG 100000
#define NPROT 100000
#define NN    100000
#define NEMAX 800000
#define DIM   128
#define KC    32        // k-chunk
#define SAKH  40        // smem chunk row stride (fp16 units, 80B: conflict-free)
#define GBLK  782       // ceil(100000/128)

// ---------------- scratch ----------------
// pre-scaled fp16 feature buffers (ping-pong A/B):
//   *_d  : drug features scaled by rsqrt(ddi_out)
//   *_p1 : protein features scaled by rsqrt(pdi_out)
//   *_p2 : protein features scaled by rsqrt(ppi_out)
__device__ __half g_sA_d [(size_t)NN * DIM];
__device__ __half g_sA_p1[(size_t)NN * DIM];
__device__ __half g_sA_p2[(size_t)NN * DIM];
__device__ __half g_sB_d [(size_t)NN * DIM];
__device__ __half g_sB_p1[(size_t)NN * DIM];
__device__ __half g_sB_p2[(size_t)NN * DIM];
__device__ __half g_agg1[(size_t)NDRUG * DIM];
__device__ __half g_agg2[(size_t)NDRUG * DIM];
__device__ __half g_aggp[(size_t)NPROT * DIM];
// int degree counts: [0]=ddi_out [1]=ddi_in [2]=pdi_out [3]=pdi_in [4]=ppi_out [5]=ppi_in
__device__ int g_cnt[6 * NN];
__device__ __half g_Wt[(size_t)9 * DIM * DIM];  // transposed fp16 weights [layer][rel][n][k]
__device__ int g_indptr[3 * (NN + 1)];
__device__ int g_cursor[3 * NN];
__device__ int g_eidx[3 * NEMAX];
__device__ int g_bsum[3 * 128];

// ---------------- helpers ----------------
__device__ __forceinline__ uint32_t sptr(const void* p) {
    return (uint32_t)__cvta_generic_to_shared(p);
}
__device__ __forceinline__ void cp_async16(uint32_t dst, const void* src, int sz) {
    asm volatile("cp.async.cg.shared.global [%0], [%1], 16, %2;" :: "r"(dst), "l"(src), "r"(sz));
}
__device__ __forceinline__ void mma_f16(float c[4], const uint32_t a[4], const uint32_t b[2]) {
    asm volatile(
        "mma.sync.aligned.m16n8k16.row.col.f32.f16.f16.f32 "
        "{%0,%1,%2,%3}, {%4,%5,%6,%7}, {%8,%9}, {%0,%1,%2,%3};"
        : "+f"(c[0]), "+f"(c[1]), "+f"(c[2]), "+f"(c[3])
        : "r"(a[0]), "r"(a[1]), "r"(a[2]), "r"(a[3]), "r"(b[0]), "r"(b[1]));
}
__device__ __forceinline__ float rs_of(int c) {
    return rsqrtf(fmaxf((float)c, 1.0f));
}

// ---------------- prep: transpose W to fp16 [n][k] + zero counts ----------------
#define PREP_X 2344
__global__ void prep_kernel(const float* __restrict__ Wa, const float* __restrict__ Wb,
                            const float* __restrict__ Wc, __half* __restrict__ Wt,
                            int* __restrict__ cnt) {
    const int y = blockIdx.y;
    if (y == 0) {
        for (int i = blockIdx.x * 256 + threadIdx.x; i < 9 * DIM * DIM; i += PREP_X * 256) {
            int grp = i / (3 * DIM * DIM);
            int rem3 = i - grp * 3 * DIM * DIM;
            const float* W = grp == 0 ? Wa : (grp == 1 ? Wb : Wc);
            int rel = rem3 >> 14, rem = rem3 & 16383;
            int k = rem >> 7, n = rem & 127;
            Wt[i - rem + (n << 7) + k] = __float2half_rn(W[(rel << 14) + (k << 7) + n]);
        }
    } else {
        int i = blockIdx.x * 256 + threadIdx.x;
        if (i < 6 * NN) cnt[i] = 0;
    }
}

// ---------------- batched degree count (int) ----------------
__global__ void count2b(const int* __restrict__ s0, const int* __restrict__ d0, int n0,
                        const int* __restrict__ s1, const int* __restrict__ d1, int n1,
                        const int* __restrict__ s2, const int* __restrict__ d2, int n2,
                        int* __restrict__ cnt) {
    const int rel = blockIdx.y;
    const int* src = rel == 0 ? s0 : (rel == 1 ? s1 : s2);
    const int* dst = rel == 0 ? d0 : (rel == 1 ? d1 : d2);
    int n = rel == 0 ? n0 : (rel == 1 ? n1 : n2);
    int* cs = cnt + (size_t)(2 * rel) * NN;
    int* cd = cnt + (size_t)(2 * rel + 1) * NN;
    int i = blockIdx.x * blockDim.x + threadIdx.x;
    if (i < n) {
        atomicAdd(&cs[src[i]], 1);
        atomicAdd(&cd[dst[i]], 1);
    }
}

// ---------------- scale fp32 inputs into pre-scaled fp16 buffers (inline rsqrt) ----------------
__global__ void scale_inputs(const float* __restrict__ fd, const float* __restrict__ fp,
                             const int* __restrict__ cnt,
                             __half* __restrict__ sd, __half* __restrict__ sp1,
                             __half* __restrict__ sp2) {
    const int y = blockIdx.y;
    const float* f    = (y == 0) ? fd : fp;
    const int* cv     = cnt + (size_t)(2 * y) * NN;   // out-counts per relation
    __half* o = (y == 0) ? sd : ((y == 1) ? sp1 : sp2);
    const int n4 = NN * DIM / 4;
    int i = blockIdx.x * blockDim.x + threadIdx.x;
    if (i < n4) {
        float sc = rs_of(__ldg(cv + (i >> 5)));
        float4 v = __ldg(reinterpret_cast<const float4*>(f) + i);
        reinterpret_cast<__half2*>(o)[2 * i]     = __floats2half2_rn(v.x * sc, v.y * sc);
        reinterpret_cast<__half2*>(o)[2 * i + 1] = __floats2half2_rn(v.z * sc, v.w * sc);
    }
}

// ---------------- scans ----------------
__global__ void scan1(const int* __restrict__ cnt, int* __restrict__ indptr,
                      int* __restrict__ bsum) {
    __shared__ int sm2[1024];
    const int rel = blockIdx.y;
    const int* c = cnt + (size_t)(2 * rel + 1) * NN;
    int* excl = indptr + rel * (NN + 1);
    int tid = threadIdx.x;
    int i = blockIdx.x * 1024 + tid;
    int v = (i < NN) ? __ldg(c + i) : 0;
    sm2[tid] = v;
    __syncthreads();
#pragma unroll
    for (int off = 1; off < 1024; off <<= 1) {
        int t2 = (tid >= off) ? sm2[tid - off] : 0;
        __syncthreads();
        sm2[tid] += t2;
        __syncthreads();
    }
    if (i < NN) excl[i] = sm2[tid] - v;
    if (tid == 1023) bsum[rel * 128 + blockIdx.x] = sm2[1023];
}
__global__ void scan3m(const int* __restrict__ cnt, int* __restrict__ indptr,
                       const int* __restrict__ bsum, int* __restrict__ cursor) {
    const int rel = blockIdx.y;
    const int* c = cnt + (size_t)(2 * rel + 1) * NN;
    int* excl = indptr + rel * (NN + 1);
    int i = blockIdx.x * blockDim.x + threadIdx.x;
    if (i < NN) {
        int b = i >> 10;
        int off = 0;
        for (int j = 0; j < b; j++) off += bsum[rel * 128 + j];
        int e = excl[i] + off;
        excl[i] = e;
        cursor[rel * NN + i] = e;
        if (i == NN - 1) excl[NN] = e + __ldg(c + i);
    }
}
// CSR fill
__global__ void fill3_kernel(const int* __restrict__ s0, const int* __restrict__ d0, int n0,
                             const int* __restrict__ s1, const int* __restrict__ d1, int n1,
                             const int* __restrict__ s2, const int* __restrict__ d2, int n2,
                             int* __restrict__ cursor, int* __restrict__ eidx) {
    const int y = blockIdx.y;
    const int* src = y == 0 ? s0 : (y == 1 ? s1 : s2);
    const int* dst = y == 0 ? d0 : (y == 1 ? d1 : d2);
    int nE = y == 0 ? n0 : (y == 1 ? n1 : n2);
    int e = blockIdx.x * blockDim.x + threadIdx.x;
    if (e < nE) {
        int p = atomicAdd(&cursor[y * NN + dst[e]], 1);
        eidx[(size_t)y * NEMAX + p] = src[e];
    }
}

// ---------------- batched CSR gather: half-warp per row (R13-proven form) ----------------
__global__ void __launch_bounds__(256)
gather3(const __half* __restrict__ sd, const __half* __restrict__ sp1,
        const __half* __restrict__ sp2,
        const int* __restrict__ indptr, const int* __restrict__ eidx,
        const int* __restrict__ cnt,
        __half* __restrict__ agg1, __half* __restrict__ agg2, __half* __restrict__ aggp) {
    const int rel = blockIdx.y;
    const __half* h = (rel == 0) ? sd : ((rel == 1) ? sp1 : sp2);
    const int* ip = indptr + rel * (NN + 1);
    const int* ei = eidx + (size_t)rel * NEMAX;
    const int* ci = cnt + (size_t)(2 * rel + 1) * NN;   // in-counts
    __half* agg = (rel == 0) ? agg1 : ((rel == 1) ? agg2 : aggp);

    int row  = (blockIdx.x * blockDim.x + threadIdx.x) >> 4;   // half-warp per row
    int lane = threadIdx.x & 15;                                // 16 lanes x 16B = 256B row
    if (row >= NN) return;
    int s0 = __ldg(ip + row), s1 = __ldg(ip + row + 1);
    float accf[8];
#pragma unroll
    for (int j = 0; j < 8; j++) accf[j] = 0.0f;

    for (int base = s0; base < s1; base += 16) {
        int m = min(16, s1 - base);
        int se = (lane < m) ? __ldg(ei + base + lane) : 0;
#pragma unroll 4
        for (int i = 0; i < m; i++) {
            int s = __shfl_sync(0xFFFFFFFFu, se, i, 16);   // segment-relative broadcast
            uint4 raw = __ldg(reinterpret_cast<const uint4*>(h + (size_t)s * DIM) + lane);
            const __half2* hh = reinterpret_cast<const __half2*>(&raw);
#pragma unroll
            for (int j = 0; j < 4; j++) {
                float2 f = __half22float2(hh[j]);
                accf[2 * j]     += f.x;
                accf[2 * j + 1] += f.y;
            }
        }
    }
    float ri = rs_of(__ldg(ci + row));
    uint4 o;
    __half2* oh = reinterpret_cast<__half2*>(&o);
#pragma unroll
    for (int j = 0; j < 4; j++)
        oh[j] = __floats2half2_rn(accf[2 * j] * ri, accf[2 * j + 1] * ri);
    reinterpret_cast<uint4*>(agg + (size_t)row * DIM)[lane] = o;
}

// ---------------- cp.async double-buffered fp16 HMMA GEMM ----------------
template<bool RELU, bool TWO, bool F16OUT>
__device__ __forceinline__ void gemm_body(
    int bx, const __half* __restrict__ A1, const __half* __restrict__ A2,
    const __half* __restrict__ Wt1, const __half* __restrict__ Wt2,
    const float* __restrict__ b1, const float* __restrict__ b2,
    void* __restrict__ out1, void* __restrict__ out2,
    const int* __restrict__ cnt1, const int* __restrict__ cnt2,
    int nrows, __half* sm) {
    __half* As = sm;
    __half* Ws = sm + 2 * 128 * SAKH;

    const int t = threadIdx.x;
    const int lane = t & 31, wid = t >> 5;
    const int wm = wid >> 2, wn = wid & 3;
    const int row0 = bx * 128;
    const int qid = lane >> 2, qtl = lane & 3;

    float acc[4][4][4];
#pragma unroll
    for (int mi = 0; mi < 4; mi++)
#pragma unroll
        for (int ni = 0; ni < 4; ni++)
#pragma unroll
            for (int j = 0; j < 4; j++) acc[mi][ni][j] = 0.0f;

    const int C = TWO ? 8 : 4;

    auto issue = [&](int c) {
        int sidx = TWO ? (c >> 2) : 0;
        int kc   = TWO ? (c & 3) : c;
        const __half* A = sidx ? A2 : A1;
        const __half* W = sidx ? Wt2 : Wt1;
        int stage = c & 1;
        __half* as = As + stage * 128 * SAKH;
        __half* ws = Ws + stage * 128 * SAKH;
#pragma unroll
        for (int i = 0; i < 2; i++) {
            int idx = t + 256 * i;
            int r = idx >> 2, c4 = idx & 3;
            int row = row0 + r;
            int sz = (row < nrows) ? 16 : 0;
            cp_async16(sptr(as + r * SAKH + c4 * 8), A + (size_t)row * DIM + kc * KC + c4 * 8, sz);
            cp_async16(sptr(ws + r * SAKH + c4 * 8), W + (size_t)r * DIM + kc * KC + c4 * 8, 16);
        }
        asm volatile("cp.async.commit_group;" ::: "memory");
    };

    issue(0);
    issue(1);
    for (int c = 0; c < C; c++) {
        if (c == C - 1) asm volatile("cp.async.wait_group 0;" ::: "memory");
        else            asm volatile("cp.async.wait_group 1;" ::: "memory");
        __syncthreads();
        const int stage = c & 1;
        const __half* as = As + stage * 128 * SAKH;
        const __half* ws = Ws + stage * 128 * SAKH;
#pragma unroll
        for (int ks = 0; ks < 2; ks++) {
            const int k0 = ks * 16;
            uint32_t a[4][4], bf[4][2];
#pragma unroll
            for (int mi = 0; mi < 4; mi++) {
                const __half* p = &as[(wm * 64 + mi * 16 + qid) * SAKH + k0 + 2 * qtl];
                a[mi][0] = *reinterpret_cast<const uint32_t*>(p);
                a[mi][1] = *reinterpret_cast<const uint32_t*>(p + 8 * SAKH);
                a[mi][2] = *reinterpret_cast<const uint32_t*>(p + 8);
                a[mi][3] = *reinterpret_cast<const uint32_t*>(p + 8 * SAKH + 8);
            }
#pragma unroll
            for (int ni = 0; ni < 4; ni++) {
                const __half* p = &ws[(wn * 32 + ni * 8 + qid) * SAKH + k0 + 2 * qtl];
                bf[ni][0] = *reinterpret_cast<const uint32_t*>(p);
                bf[ni][1] = *reinterpret_cast<const uint32_t*>(p + 8);
            }
#pragma unroll
            for (int mi = 0; mi < 4; mi++)
#pragma unroll
                for (int ni = 0; ni < 4; ni++)
                    mma_f16(acc[mi][ni], a[mi], bf[ni]);
        }
        __syncthreads();
        if (c + 2 < C) issue(c + 2);
    }

    // Epilogue
#pragma unroll
    for (int ni = 0; ni < 4; ni++) {
        int col = wn * 32 + ni * 8 + qtl * 2;
        float bb0 = __ldg(b1 + col)     + (TWO ? __ldg(b2 + col)     : 0.0f);
        float bb1 = __ldg(b1 + col + 1) + (TWO ? __ldg(b2 + col + 1) : 0.0f);
#pragma unroll
        for (int mi = 0; mi < 4; mi++) {
#pragma unroll
            for (int half = 0; half < 2; half++) {
                int r = row0 + wm * 64 + mi * 16 + qid + half * 8;
                if (r < nrows) {
                    float ox = acc[mi][ni][half * 2 + 0] + bb0;
                    float oy = acc[mi][ni][half * 2 + 1] + bb1;
                    if (RELU) { ox = fmaxf(ox, 0.0f); oy = fmaxf(oy, 0.0f); }
                    if (F16OUT) {
                        float sA = rs_of(__ldg(cnt1 + r));
                        *reinterpret_cast<__half2*>(
                            (__half*)out1 + (size_t)r * DIM + col) =
                            __floats2half2_rn(ox * sA, oy * sA);
                        if (!TWO) {
                            float sB = rs_of(__ldg(cnt2 + r));
                            *reinterpret_cast<__half2*>(
                                (__half*)out2 + (size_t)r * DIM + col) =
                                __floats2half2_rn(ox * sB, oy * sB);
                        }
                    } else {
                        float2 o; o.x = ox; o.y = oy;
                        *reinterpret_cast<float2*>((float*)out1 + (size_t)r * DIM + col) = o;
                    }
                }
            }
        }
    }
}

template<bool RELU, bool F16OUT>
__global__ void __launch_bounds__(256)
layer_mma(const __half* __restrict__ agg1, const __half* __restrict__ agg2,
          const __half* __restrict__ aggp, const __half* __restrict__ Wt,
          const float* __restrict__ bb, const int* __restrict__ cnt,
          void* __restrict__ outd, void* __restrict__ outp1, void* __restrict__ outp2,
          int split) {
    extern __shared__ __half smh[];
    if ((int)blockIdx.x < split)
        gemm_body<RELU, true, F16OUT>(blockIdx.x, agg1, agg2,
                                      Wt, Wt + DIM * DIM, bb, bb + DIM,
                                      outd, nullptr, cnt + 0 * NN, nullptr, NDRUG, smh);
    else
        gemm_body<RELU, false, F16OUT>(blockIdx.x - split, aggp, nullptr,
                                       Wt + 2 * DIM * DIM, nullptr, bb + 2 * DIM, nullptr,
                                       outp1, outp2, cnt + 2 * NN, cnt + 4 * NN, NPROT, smh);
}

// ---------------- host orchestration ----------------
static const size_t GEMM_SMEM = 4u * 128u * SAKH * sizeof(__half);  // 40960 B

template<bool RELU, bool F16OUT>
static void launch_layer(const __half* sd, const __half* sp1, const __half* sp2,
                         void* od, void* op1, void* op2,
                         const __half* Wt, const float* b,
                         int* indptr, int* eidx,
                         __half* agg1, __half* agg2, __half* aggp, int* cnt) {
    gather3<<<dim3((NN * 16 + 255) / 256, 3), 256>>>(sd, sp1, sp2, indptr, eidx, cnt,
                                                     agg1, agg2, aggp);
    layer_mma<RELU, F16OUT><<<2 * GBLK, 256, GEMM_SMEM>>>(agg1, agg2, aggp, Wt, b, cnt,
                                                          od, op1, op2, GBLK);
}

extern "C" void kernel_launch(void* const* d_in, const int* in_sizes, int n_in,
                              void* d_out, int out_size) {
    const float* hd0   = (const float*)d_in[0];
    const float* hp0   = (const float*)d_in[1];
    const int*   ddi_s = (const int*)d_in[2];
    const int*   ddi_d = (const int*)d_in[3];
    const int*   pdi_s = (const int*)d_in[4];
    const int*   pdi_d = (const int*)d_in[5];
    const int*   ppi_s = (const int*)d_in[6];
    const int*   ppi_d = (const int*)d_in[7];
    const float* W1 = (const float*)d_in[8];
    const float* b1 = (const float*)d_in[9];
    const float* W2 = (const float*)d_in[10];
    const float* b2 = (const float*)d_in[11];
    const float* W3 = (const float*)d_in[12];
    const float* b3 = (const float*)d_in[13];

    const int nE_ddi = in_sizes[2];
    const int nE_pdi = in_sizes[4];
    const int nE_ppi = in_sizes[6];

    cudaFuncSetAttribute(layer_mma<true, true>,   cudaFuncAttributeMaxDynamicSharedMemorySize, (int)GEMM_SMEM);
    cudaFuncSetAttribute(layer_mma<false, false>, cudaFuncAttributeMaxDynamicSharedMemorySize, (int)GEMM_SMEM);

    __half *agg1, *agg2, *aggp, *wt;
    __half *sA_d, *sA_p1, *sA_p2, *sB_d, *sB_p1, *sB_p2;
    int *cnt, *indptr, *cursor, *eidx, *bsum;
    cudaGetSymbolAddress((void**)&sA_d,  g_sA_d);
    cudaGetSymbolAddress((void**)&sA_p1, g_sA_p1);
    cudaGetSymbolAddress((void**)&sA_p2, g_sA_p2);
    cudaGetSymbolAddress((void**)&sB_d,  g_sB_d);
    cudaGetSymbolAddress((void**)&sB_p1, g_sB_p1);
    cudaGetSymbolAddress((void**)&sB_p2, g_sB_p2);
    cudaGetSymbolAddress((void**)&agg1, g_agg1);
    cudaGetSymbolAddress((void**)&agg2, g_agg2);
    cudaGetSymbolAddress((void**)&aggp, g_aggp);
    cudaGetSymbolAddress((void**)&cnt, g_cnt);
    cudaGetSymbolAddress((void**)&wt, g_Wt);
    cudaGetSymbolAddress((void**)&indptr, g_indptr);
    cudaGetSymbolAddress((void**)&cursor, g_cursor);
    cudaGetSymbolAddress((void**)&eidx, g_eidx);
    cudaGetSymbolAddress((void**)&bsum, g_bsum);

    int nEmax = nE_ddi > nE_pdi ? nE_ddi : nE_pdi;
    if (nE_ppi > nEmax) nEmax = nE_ppi;

    // preprocessing
    prep_kernel<<<dim3(PREP_X, 2), 256>>>(W1, W2, W3, wt, cnt);
    count2b<<<dim3((nEmax + 255) / 256, 3), 256>>>(
        ddi_s, ddi_d, nE_ddi, pdi_s, pdi_d, nE_pdi, ppi_s, ppi_d, nE_ppi, cnt);
    scale_inputs<<<dim3((NN * DIM / 4 + 255) / 256, 3), 256>>>(
        hd0, hp0, cnt, sA_d, sA_p1, sA_p2);
    scan1<<<dim3((NN + 1023) / 1024, 3), 1024>>>(cnt, indptr, bsum);
    scan3m<<<dim3((NN + 255) / 256, 3), 256>>>(cnt, indptr, bsum, cursor);
    fill3_kernel<<<dim3((nEmax + 255) / 256, 3), 256>>>(
        ddi_s, ddi_d, nE_ddi, pdi_s, pdi_d, nE_pdi, ppi_s, ppi_d, nE_ppi, cursor, eidx);

    float* outd = (float*)d_out;
    float* outp = outd + (size_t)NDRUG * DIM;

    // layer 1: A -> B (pre-scaled fp16), ReLU
    launch_layer<true, true>(sA_d, sA_p1, sA_p2, sB_d, sB_p1, sB_p2,
                             wt + 0 * 3 * DIM * DIM, b1, indptr, eidx, agg1, agg2, aggp, cnt);
    // layer 2: B -> A, ReLU
    launch_layer<true, true>(sB_d, sB_p1, sB_p2, sA_d, sA_p1, sA_p2,
                             wt + 1 * 3 * DIM * DIM, b2, indptr, eidx, agg1, agg2, aggp, cnt);
    // layer 3: A -> fp32 d_out, no activation
    launch_layer<false, false>(sA_d, sA_p1, sA_p2, outd, outp, nullptr,
                               wt + 2 * 3 * DIM * DIM, b3, indptr, eidx, agg1, agg2, aggp, cnt);
}

// round 16
// speedup vs baseline: 1.4143x; 1.0305x over previous
#include <cuda_runtime.h>
#include <cuda_fp16.h>
#include <cstdint>

#define NDRUG 100000
#define NPROT 100000
#define NN    100000
#define NEMAX 800000
#define DIM   128
#define KC    32        // k-chunk
#define SAKH  40        // smem chunk row stride (fp16 units, 80B: conflict-free)
#define GBLK  782       // ceil(100000/128)

// ---------------- scratch ----------------
// pre-scaled fp16 feature buffers (ping-pong A/B):
//   *_d  : drug features scaled by rs_ddi_out
//   *_p1 : protein features scaled by rs_pdi_out
//   *_p2 : protein features scaled by rs_ppi_out
__device__ __half g_sA_d [(size_t)NN * DIM];
__device__ __half g_sA_p1[(size_t)NN * DIM];
__device__ __half g_sA_p2[(size_t)NN * DIM];
__device__ __half g_sB_d [(size_t)NN * DIM];
__device__ __half g_sB_p1[(size_t)NN * DIM];
__device__ __half g_sB_p2[(size_t)NN * DIM];
__device__ __half g_agg1[(size_t)NDRUG * DIM];
__device__ __half g_agg2[(size_t)NDRUG * DIM];
__device__ __half g_aggp[(size_t)NPROT * DIM];
// [0]=ddi_out [1]=ddi_in [2]=pdi_out [3]=pdi_in [4]=ppi_out [5]=ppi_in
__device__ float g_rs[(size_t)6 * NN];
__device__ __half g_Wt[(size_t)9 * DIM * DIM];  // transposed fp16 weights [layer][rel][n][k]
__device__ int g_indptr[3 * (NN + 1)];
__device__ int g_cursor[3 * NN];
__device__ int g_eidx[3 * NEMAX];
__device__ int g_bsum[3 * 128];

// ---------------- helpers ----------------
__device__ __forceinline__ uint32_t sptr(const void* p) {
    return (uint32_t)__cvta_generic_to_shared(p);
}
__device__ __forceinline__ void cp_async16(uint32_t dst, const void* src, int sz) {
    asm volatile("cp.async.cg.shared.global [%0], [%1], 16, %2;" :: "r"(dst), "l"(src), "r"(sz));
}
__device__ __forceinline__ void mma_f16(float c[4], const uint32_t a[4], const uint32_t b[2]) {
    asm volatile(
        "mma.sync.aligned.m16n8k16.row.col.f32.f16.f16.f32 "
        "{%0,%1,%2,%3}, {%4,%5,%6,%7}, {%8,%9}, {%0,%1,%2,%3};"
        : "+f"(c[0]), "+f"(c[1]), "+f"(c[2]), "+f"(c[3])
        : "r"(a[0]), "r"(a[1]), "r"(a[2]), "r"(a[3]), "r"(b[0]), "r"(b[1]));
}

// ---------------- prep: transpose W to fp16 [n][k] + zero rs ----------------
#define PREP_X 2344
__global__ void prep_kernel(const float* __restrict__ Wa, const float* __restrict__ Wb,
                            const float* __restrict__ Wc, __half* __restrict__ Wt,
                            float* __restrict__ rs) {
    const int y = blockIdx.y;
    if (y == 0) {          // transpose+convert 9 weight matrices
        for (int i = blockIdx.x * 256 + threadIdx.x; i < 9 * DIM * DIM; i += PREP_X * 256) {
            int grp = i / (3 * DIM * DIM);
            int rem3 = i - grp * 3 * DIM * DIM;
            const float* W = grp == 0 ? Wa : (grp == 1 ? Wb : Wc);
            int rel = rem3 >> 14, rem = rem3 & 16383;
            int k = rem >> 7, n = rem & 127;
            Wt[i - rem + (n << 7) + k] = __float2half_rn(W[(rel << 14) + (k << 7) + n]);
        }
    } else {               // zero rs
        int i = blockIdx.x * 256 + threadIdx.x;
        if (i < 6 * NN) rs[i] = 0.0f;
    }
}

// ---------------- batched degree count ----------------
__global__ void count2b(const int* __restrict__ s0, const int* __restrict__ d0, int n0,
                        const int* __restrict__ s1, const int* __restrict__ d1, int n1,
                        const int* __restrict__ s2, const int* __restrict__ d2, int n2,
                        float* __restrict__ rs) {
    const int rel = blockIdx.y;
    const int* src = rel == 0 ? s0 : (rel == 1 ? s1 : s2);
    const int* dst = rel == 0 ? d0 : (rel == 1 ? d1 : d2);
    int n = rel == 0 ? n0 : (rel == 1 ? n1 : n2);
    float* cs = rs + (size_t)(2 * rel) * NN;
    float* cd = rs + (size_t)(2 * rel + 1) * NN;
    int i = blockIdx.x * blockDim.x + threadIdx.x;
    if (i < n) {
        atomicAdd(&cs[src[i]], 1.0f);
        atomicAdd(&cd[dst[i]], 1.0f);
    }
}

// ---------------- scans ----------------
__global__ void scan1(const float* __restrict__ rs, int* __restrict__ indptr,
                      int* __restrict__ bsum) {
    __shared__ int sm2[1024];
    const int rel = blockIdx.y;
    const float* cnt = rs + (size_t)(2 * rel + 1) * NN;
    int* excl = indptr + rel * (NN + 1);
    int tid = threadIdx.x;
    int i = blockIdx.x * 1024 + tid;
    int v = (i < NN) ? (int)cnt[i] : 0;
    sm2[tid] = v;
    __syncthreads();
#pragma unroll
    for (int off = 1; off < 1024; off <<= 1) {
        int t2 = (tid >= off) ? sm2[tid - off] : 0;
        __syncthreads();
        sm2[tid] += t2;
        __syncthreads();
    }
    if (i < NN) excl[i] = sm2[tid] - v;
    if (tid == 1023) bsum[rel * 128 + blockIdx.x] = sm2[1023];
}
__global__ void scan3m(const float* __restrict__ rs, int* __restrict__ indptr,
                       const int* __restrict__ bsum, int* __restrict__ cursor) {
    const int rel = blockIdx.y;
    const float* cnt = rs + (size_t)(2 * rel + 1) * NN;
    int* excl = indptr + rel * (NN + 1);
    int i = blockIdx.x * blockDim.x + threadIdx.x;
    if (i < NN) {
        int b = i >> 10;
        int off = 0;
        for (int j = 0; j < b; j++) off += bsum[rel * 128 + j];
        int e = excl[i] + off;
        excl[i] = e;
        cursor[rel * NN + i] = e;
        if (i == NN - 1) excl[NN] = e + (int)cnt[i];
    }
}
// CSR fill (y=0..2) + rsqrt (y=3)
__global__ void fillr_kernel(const int* __restrict__ s0, const int* __restrict__ d0, int n0,
                             const int* __restrict__ s1, const int* __restrict__ d1, int n1,
                             const int* __restrict__ s2, const int* __restrict__ d2, int n2,
                             int* __restrict__ cursor, int* __restrict__ eidx,
                             float* __restrict__ rs) {
    const int y = blockIdx.y;
    if (y < 3) {
        const int* src = y == 0 ? s0 : (y == 1 ? s1 : s2);
        const int* dst = y == 0 ? d0 : (y == 1 ? d1 : d2);
        int nE = y == 0 ? n0 : (y == 1 ? n1 : n2);
        int e = blockIdx.x * blockDim.x + threadIdx.x;
        if (e < nE) {
            int p = atomicAdd(&cursor[y * NN + dst[e]], 1);
            eidx[(size_t)y * NEMAX + p] = src[e];
        }
    } else {
        int i = blockIdx.x * blockDim.x + threadIdx.x;
        if (i < 6 * NN) rs[i] = rsqrtf(fmaxf(rs[i], 1.0f));
    }
}

// ---------------- scale fp32 inputs into the 3 pre-scaled fp16 buffers ----------------
// y=0: drug*rs_ddi_out -> sd ; y=1: prot*rs_pdi_out -> sp1 ; y=2: prot*rs_ppi_out -> sp2
__global__ void scale_inputs(const float* __restrict__ fd, const float* __restrict__ fp,
                             const float* __restrict__ rs,
                             __half* __restrict__ sd, __half* __restrict__ sp1,
                             __half* __restrict__ sp2) {
    const int y = blockIdx.y;
    const float* f   = (y == 0) ? fd : fp;
    const float* rsv = rs + (size_t)(2 * y) * NN;   // ddi_out / pdi_out / ppi_out
    __half* o = (y == 0) ? sd : ((y == 1) ? sp1 : sp2);
    const int n4 = NN * DIM / 4;
    int i = blockIdx.x * blockDim.x + threadIdx.x;
    if (i < n4) {
        float sc = __ldg(rsv + (i >> 5));           // 32 float4 per row
        float4 v = __ldg(reinterpret_cast<const float4*>(f) + i);
        reinterpret_cast<__half2*>(o)[2 * i]     = __floats2half2_rn(v.x * sc, v.y * sc);
        reinterpret_cast<__half2*>(o)[2 * i + 1] = __floats2half2_rn(v.z * sc, v.w * sc);
    }
}

// ---------------- batched CSR gather: half-warp per dst row, pre-scaled features ----------------
__global__ void __launch_bounds__(256)
gather3(const __half* __restrict__ sd, const __half* __restrict__ sp1,
        const __half* __restrict__ sp2,
        const int* __restrict__ indptr, const int* __restrict__ eidx,
        const float* __restrict__ rs,
        __half* __restrict__ agg1, __half* __restrict__ agg2, __half* __restrict__ aggp) {
    const int rel = blockIdx.y;
    const __half* h = (rel == 0) ? sd : ((rel == 1) ? sp1 : sp2);
    const int*   ip  = indptr + rel * (NN + 1);
    const int*   ei  = eidx + (size_t)rel * NEMAX;
    const float* rsi = rs + (size_t)(2 * rel + 1) * NN;
    __half* agg = (rel == 0) ? agg1 : ((rel == 1) ? agg2 : aggp);

    int row  = (blockIdx.x * blockDim.x + threadIdx.x) >> 4;   // half-warp per row
    int lane = threadIdx.x & 15;                                // 16 lanes x 16B = 256B row
    if (row >= NN) return;
    int s0 = __ldg(ip + row), s1 = __ldg(ip + row + 1);
    float accf[8];
#pragma unroll
    for (int j = 0; j < 8; j++) accf[j] = 0.0f;

    for (int base = s0; base < s1; base += 16) {
        int m = min(16, s1 - base);
        int se = (lane < m) ? __ldg(ei + base + lane) : 0;
#pragma unroll 4
        for (int i = 0; i < m; i++) {
            int s = __shfl_sync(0xFFFFFFFFu, se, i, 16);   // segment-relative broadcast
            uint4 raw = __ldg(reinterpret_cast<const uint4*>(h + (size_t)s * DIM) + lane);
            const __half2* hh = reinterpret_cast<const __half2*>(&raw);
#pragma unroll
            for (int j = 0; j < 4; j++) {
                float2 f = __half22float2(hh[j]);
                accf[2 * j]     += f.x;
                accf[2 * j + 1] += f.y;
            }
        }
    }
    float ri = __ldg(rsi + row);
    uint4 o;
    __half2* oh = reinterpret_cast<__half2*>(&o);
#pragma unroll
    for (int j = 0; j < 4; j++)
        oh[j] = __floats2half2_rn(accf[2 * j] * ri, accf[2 * j + 1] * ri);
    reinterpret_cast<uint4*>(agg + (size_t)row * DIM)[lane] = o;
}

// ---------------- cp.async double-buffered fp16 HMMA GEMM ----------------
// F16OUT layers write PRE-SCALED fp16 feature copies:
//   drug (TWO=true): out1 = feat * rso1  (ddi_out)
//   prot (TWO=false): out1 = feat * rso1 (pdi_out), out2 = feat * rso2 (ppi_out)
// Final layer (F16OUT=false): fp32 unscaled to out1.
template<bool RELU, bool TWO, bool F16OUT>
__device__ __forceinline__ void gemm_body(
    int bx, const __half* __restrict__ A1, const __half* __restrict__ A2,
    const __half* __restrict__ Wt1, const __half* __restrict__ Wt2,
    const float* __restrict__ b1, const float* __restrict__ b2,
    void* __restrict__ out1, void* __restrict__ out2,
    const float* __restrict__ rso1, const float* __restrict__ rso2,
    int nrows, __half* sm) {
    __half* As = sm;                       // [2][128][SAKH]
    __half* Ws = sm + 2 * 128 * SAKH;      // [2][128][SAKH]

    const int t = threadIdx.x;
    const int lane = t & 31, wid = t >> 5;
    const int wm = wid >> 2, wn = wid & 3;
    const int row0 = bx * 128;
    const int qid = lane >> 2, qtl = lane & 3;

    float acc[4][4][4];
#pragma unroll
    for (int mi = 0; mi < 4; mi++)
#pragma unroll
        for (int ni = 0; ni < 4; ni++)
#pragma unroll
            for (int j = 0; j < 4; j++) acc[mi][ni][j] = 0.0f;

    const int C = TWO ? 8 : 4;

    auto issue = [&](int c) {
        int sidx = TWO ? (c >> 2) : 0;
        int kc   = TWO ? (c & 3) : c;
        const __half* A = sidx ? A2 : A1;
        const __half* W = sidx ? Wt2 : Wt1;
        int stage = c & 1;
        __half* as = As + stage * 128 * SAKH;
        __half* ws = Ws + stage * 128 * SAKH;
#pragma unroll
        for (int i = 0; i < 2; i++) {
            int idx = t + 256 * i;
            int r = idx >> 2, c4 = idx & 3;
            int row = row0 + r;
            int sz = (row < nrows) ? 16 : 0;
            cp_async16(sptr(as + r * SAKH + c4 * 8), A + (size_t)row * DIM + kc * KC + c4 * 8, sz);
            cp_async16(sptr(ws + r * SAKH + c4 * 8), W + (size_t)r * DIM + kc * KC + c4 * 8, 16);
        }
        asm volatile("cp.async.commit_group;" ::: "memory");
    };

    issue(0);
    issue(1);
    for (int c = 0; c < C; c++) {
        if (c == C - 1) asm volatile("cp.async.wait_group 0;" ::: "memory");
        else            asm volatile("cp.async.wait_group 1;" ::: "memory");
        __syncthreads();
        const int stage = c & 1;
        const __half* as = As + stage * 128 * SAKH;
        const __half* ws = Ws + stage * 128 * SAKH;
#pragma unroll
        for (int ks = 0; ks < 2; ks++) {
            const int k0 = ks * 16;
            uint32_t a[4][4], bf[4][2];
#pragma unroll
            for (int mi = 0; mi < 4; mi++) {
                const __half* p = &as[(wm * 64 + mi * 16 + qid) * SAKH + k0 + 2 * qtl];
                a[mi][0] = *reinterpret_cast<const uint32_t*>(p);
                a[mi][1] = *reinterpret_cast<const uint32_t*>(p + 8 * SAKH);
                a[mi][2] = *reinterpret_cast<const uint32_t*>(p + 8);
                a[mi][3] = *reinterpret_cast<const uint32_t*>(p + 8 * SAKH + 8);
            }
#pragma unroll
            for (int ni = 0; ni < 4; ni++) {
                const __half* p = &ws[(wn * 32 + ni * 8 + qid) * SAKH + k0 + 2 * qtl];
                bf[ni][0] = *reinterpret_cast<const uint32_t*>(p);
                bf[ni][1] = *reinterpret_cast<const uint32_t*>(p + 8);
            }
#pragma unroll
            for (int mi = 0; mi < 4; mi++)
#pragma unroll
                for (int ni = 0; ni < 4; ni++)
                    mma_f16(acc[mi][ni], a[mi], bf[ni]);
        }
        __syncthreads();
        if (c + 2 < C) issue(c + 2);
    }

    // Epilogue
#pragma unroll
    for (int ni = 0; ni < 4; ni++) {
        int col = wn * 32 + ni * 8 + qtl * 2;
        float bb0 = __ldg(b1 + col)     + (TWO ? __ldg(b2 + col)     : 0.0f);
        float bb1 = __ldg(b1 + col + 1) + (TWO ? __ldg(b2 + col + 1) : 0.0f);
#pragma unroll
        for (int mi = 0; mi < 4; mi++) {
#pragma unroll
            for (int half = 0; half < 2; half++) {
                int r = row0 + wm * 64 + mi * 16 + qid + half * 8;
                if (r < nrows) {
                    float ox = acc[mi][ni][half * 2 + 0] + bb0;
                    float oy = acc[mi][ni][half * 2 + 1] + bb1;
                    if (RELU) { ox = fmaxf(ox, 0.0f); oy = fmaxf(oy, 0.0f); }
                    if (F16OUT) {
                        float sA = __ldg(rso1 + r);
                        *reinterpret_cast<__half2*>(
                            (__half*)out1 + (size_t)r * DIM + col) =
                            __floats2half2_rn(ox * sA, oy * sA);
                        if (!TWO) {
                            float sB = __ldg(rso2 + r);
                            *reinterpret_cast<__half2*>(
                                (__half*)out2 + (size_t)r * DIM + col) =
                                __floats2half2_rn(ox * sB, oy * sB);
                        }
                    } else {
                        float2 o; o.x = ox; o.y = oy;
                        *reinterpret_cast<float2*>((float*)out1 + (size_t)r * DIM + col) = o;
                    }
                }
            }
        }
    }
}

template<bool RELU, bool F16OUT>
__global__ void __launch_bounds__(256)
layer_mma(const __half* __restrict__ agg1, const __half* __restrict__ agg2,
          const __half* __restrict__ aggp, const __half* __restrict__ Wt,
          const float* __restrict__ bb, const float* __restrict__ rs,
          void* __restrict__ outd, void* __restrict__ outp1, void* __restrict__ outp2,
          int split) {
    extern __shared__ __half smh[];
    if ((int)blockIdx.x < split)
        gemm_body<RELU, true, F16OUT>(blockIdx.x, agg1, agg2,
                                      Wt, Wt + DIM * DIM, bb, bb + DIM,
                                      outd, nullptr, rs + 0 * NN, nullptr, NDRUG, smh);
    else
        gemm_body<RELU, false, F16OUT>(blockIdx.x - split, aggp, nullptr,
                                       Wt + 2 * DIM * DIM, nullptr, bb + 2 * DIM, nullptr,
                                       outp1, outp2, rs + 2 * NN, rs + 4 * NN, NPROT, smh);
}

// ---------------- host orchestration ----------------
static const size_t GEMM_SMEM = 4u * 128u * SAKH * sizeof(__half);  // 40960 B

template<bool RELU, bool F16OUT>
static void launch_layer(const __half* sd, const __half* sp1, const __half* sp2,
                         void* od, void* op1, void* op2,
                         const __half* Wt, const float* b,
                         int* indptr, int* eidx,
                         __half* agg1, __half* agg2, __half* aggp, float* rs) {
    gather3<<<dim3((NN * 16 + 255) / 256, 3), 256>>>(sd, sp1, sp2, indptr, eidx, rs,
                                                     agg1, agg2, aggp);
    layer_mma<RELU, F16OUT><<<2 * GBLK, 256, GEMM_SMEM>>>(agg1, agg2, aggp, Wt, b, rs,
                                                          od, op1, op2, GBLK);
}

extern "C" void kernel_launch(void* const* d_in, const int* in_sizes, int n_in,
                              void* d_out, int out_size) {
    const float* hd0   = (const float*)d_in[0];
    const float* hp0   = (const float*)d_in[1];
    const int*   ddi_s = (const int*)d_in[2];
    const int*   ddi_d = (const int*)d_in[3];
    const int*   pdi_s = (const int*)d_in[4];
    const int*   pdi_d = (const int*)d_in[5];
    const int*   ppi_s = (const int*)d_in[6];
    const int*   ppi_d = (const int*)d_in[7];
    const float* W1 = (const float*)d_in[8];
    const float* b1 = (const float*)d_in[9];
    const float* W2 = (const float*)d_in[10];
    const float* b2 = (const float*)d_in[11];
    const float* W3 = (const float*)d_in[12];
    const float* b3 = (const float*)d_in[13];

    const int nE_ddi = in_sizes[2];
    const int nE_pdi = in_sizes[4];
    const int nE_ppi = in_sizes[6];

    cudaFuncSetAttribute(layer_mma<true, true>,   cudaFuncAttributeMaxDynamicSharedMemorySize, (int)GEMM_SMEM);
    cudaFuncSetAttribute(layer_mma<false, false>, cudaFuncAttributeMaxDynamicSharedMemorySize, (int)GEMM_SMEM);

    float *rs;
    __half *agg1, *agg2, *aggp, *wt;
    __half *sA_d, *sA_p1, *sA_p2, *sB_d, *sB_p1, *sB_p2;
    int *indptr, *cursor, *eidx, *bsum;
    cudaGetSymbolAddress((void**)&sA_d,  g_sA_d);
    cudaGetSymbolAddress((void**)&sA_p1, g_sA_p1);
    cudaGetSymbolAddress((void**)&sA_p2, g_sA_p2);
    cudaGetSymbolAddress((void**)&sB_d,  g_sB_d);
    cudaGetSymbolAddress((void**)&sB_p1, g_sB_p1);
    cudaGetSymbolAddress((void**)&sB_p2, g_sB_p2);
    cudaGetSymbolAddress((void**)&agg1, g_agg1);
    cudaGetSymbolAddress((void**)&agg2, g_agg2);
    cudaGetSymbolAddress((void**)&aggp, g_aggp);
    cudaGetSymbolAddress((void**)&rs, g_rs);
    cudaGetSymbolAddress((void**)&wt, g_Wt);
    cudaGetSymbolAddress((void**)&indptr, g_indptr);
    cudaGetSymbolAddress((void**)&cursor, g_cursor);
    cudaGetSymbolAddress((void**)&eidx, g_eidx);
    cudaGetSymbolAddress((void**)&bsum, g_bsum);

    int nEmax = nE_ddi > nE_pdi ? nE_ddi : nE_pdi;
    if (nE_ppi > nEmax) nEmax = nE_ppi;

    // preprocessing
    prep_kernel<<<dim3(PREP_X, 2), 256>>>(W1, W2, W3, wt, rs);
    count2b<<<dim3((nEmax + 255) / 256, 3), 256>>>(
        ddi_s, ddi_d, nE_ddi, pdi_s, pdi_d, nE_pdi, ppi_s, ppi_d, nE_ppi, rs);
    scan1<<<dim3((NN + 1023) / 1024, 3), 1024>>>(rs, indptr, bsum);
    scan3m<<<dim3((NN + 255) / 256, 3), 256>>>(rs, indptr, bsum, cursor);
    fillr_kernel<<<dim3((nEmax + 255) / 256, 4), 256>>>(
        ddi_s, ddi_d, nE_ddi, pdi_s, pdi_d, nE_pdi, ppi_s, ppi_d, nE_ppi, cursor, eidx, rs);
    scale_inputs<<<dim3((NN * DIM / 4 + 255) / 256, 3), 256>>>(
        hd0, hp0, rs, sA_d, sA_p1, sA_p2);

    float* outd = (float*)d_out;
    float* outp = outd + (size_t)NDRUG * DIM;

    // layer 1: A -> B (pre-scaled fp16), ReLU
    launch_layer<true, true>(sA_d, sA_p1, sA_p2, sB_d, sB_p1, sB_p2,
                             wt + 0 * 3 * DIM * DIM, b1, indptr, eidx, agg1, agg2, aggp, rs);
    // layer 2: B -> A, ReLU
    launch_layer<true, true>(sB_d, sB_p1, sB_p2, sA_d, sA_p1, sA_p2,
                             wt + 1 * 3 * DIM * DIM, b2, indptr, eidx, agg1, agg2, aggp, rs);
    // layer 3: A -> fp32 d_out, no activation
    launch_layer<false, false>(sA_d, sA_p1, sA_p2, outd, outp, nullptr,
                               wt + 2 * 3 * DIM * DIM, b3, indptr, eidx, agg1, agg2, aggp, rs);
}